// round 2
// baseline (speedup 1.0000x reference)
#include <cuda_runtime.h>
#include <cuda_bf16.h>
#include <cstdint>

// Problem constants (fixed by setup_inputs): N=100000, F=128, H=64, E=1600000
#define FDIM 128
#define HDIM 64
#define MAXN 100096
#define MAXE 1600000

// Scratch (device globals — allocation-free per harness rules)
__device__ float g_h[(size_t)MAXN * HDIM];    // x @ W1
__device__ float g_agg[(size_t)MAXN * HDIM];  // aggregated layer-1 messages
__device__ float g_deg[MAXN];
__device__ float g_dinv[MAXN];
__device__ float g_s[MAXN];                   // per-node scalar after layer-2 linear
__device__ int   g_row[MAXE];
__device__ int   g_col[MAXE];
__device__ int   g_is64;

__device__ __forceinline__ void red_add_v4(float* addr, float4 v) {
    asm volatile("red.global.add.v4.f32 [%0], {%1, %2, %3, %4};"
                 :: "l"(addr), "f"(v.x), "f"(v.y), "f"(v.z), "f"(v.w)
                 : "memory");
}

// K_detect: decide whether edge_index buffer is int64 or int32.
// If int64 (little-endian), every odd 32-bit word is the high half of a value
// in [0, N) -> 0. If int32, odd words are random node ids.
__global__ void k_detect(const int* __restrict__ raw, int E) {
    __shared__ int any_nonzero;
    if (threadIdx.x == 0) any_nonzero = 0;
    __syncthreads();
    // sample 256 odd words spread over the 2E-word (if int32) region
    const int stride = (2 * E) / 256;
    int idx = 2 * (threadIdx.x * (stride / 2)) + 1;   // odd index
    if (idx < 2 * E && raw[idx] != 0) atomicOr(&any_nonzero, 1);
    __syncthreads();
    if (threadIdx.x == 0) g_is64 = any_nonzero ? 0 : 1;
}

// K_convert: materialize int32 row/col arrays from either dtype.
__global__ void k_convert(const void* __restrict__ raw, int* __restrict__ row,
                          int* __restrict__ col, int E) {
    const int e = blockIdx.x * blockDim.x + threadIdx.x;
    if (e >= E) return;
    if (g_is64) {
        const long long* p = (const long long*)raw;
        row[e] = (int)p[e];
        col[e] = (int)p[(size_t)E + e];
    } else {
        const int* p = (const int*)raw;
        row[e] = p[e];
        col[e] = p[(size_t)E + e];
    }
}

// K0: deg = 1 (self loop)
__global__ void k_deg_init(float* deg, int N) {
    int i = blockIdx.x * blockDim.x + threadIdx.x;
    if (i < N) deg[i] = 1.0f;
}

// K1: deg[col[e]] += 1
__global__ void k_deg_count(const int* __restrict__ col, float* deg, int E) {
    int e = blockIdx.x * blockDim.x + threadIdx.x;
    if (e < E) atomicAdd(&deg[col[e]], 1.0f);
}

// K2: dinv = rsqrt(deg)   (deg >= 1 always, self-loop)
__global__ void k_dinv(const float* __restrict__ deg, float* dinv, int N) {
    int i = blockIdx.x * blockDim.x + threadIdx.x;
    if (i < N) dinv[i] = rsqrtf(deg[i]);
}

// K3: h = x @ W1 ; agg = h * dinv^2 (self-loop contribution as init)
// 64 threads/block (one per output col), 16 rows per block, register-blocked.
__global__ void k_gemm1(const float* __restrict__ x, const float* __restrict__ W1,
                        const float* __restrict__ dinv,
                        float* __restrict__ h, float* __restrict__ agg, int N) {
    __shared__ float Ws[FDIM * HDIM];  // 32KB
    for (int i = threadIdx.x; i < FDIM * HDIM; i += blockDim.x) Ws[i] = W1[i];
    __syncthreads();

    const int c = threadIdx.x;          // 0..63
    const int row0 = blockIdx.x * 16;
    float acc[16];
#pragma unroll
    for (int r = 0; r < 16; r++) acc[r] = 0.0f;

    const int rows = min(16, N - row0);
    if (rows == 16) {
        for (int k = 0; k < FDIM; k += 4) {
            const float w0 = Ws[(k + 0) * HDIM + c];
            const float w1 = Ws[(k + 1) * HDIM + c];
            const float w2 = Ws[(k + 2) * HDIM + c];
            const float w3 = Ws[(k + 3) * HDIM + c];
#pragma unroll
            for (int r = 0; r < 16; r++) {
                const float4 xv = *reinterpret_cast<const float4*>(
                    &x[(size_t)(row0 + r) * FDIM + k]);
                acc[r] += xv.x * w0;
                acc[r] += xv.y * w1;
                acc[r] += xv.z * w2;
                acc[r] += xv.w * w3;
            }
        }
#pragma unroll
        for (int r = 0; r < 16; r++) {
            const int n = row0 + r;
            const float v = acc[r];
            const float d = dinv[n];
            h[(size_t)n * HDIM + c] = v;
            agg[(size_t)n * HDIM + c] = v * d * d;
        }
    } else {
        for (int r = 0; r < rows; r++) {
            const int n = row0 + r;
            float a = 0.0f;
            for (int k = 0; k < FDIM; k++) a += x[(size_t)n * FDIM + k] * Ws[k * HDIM + c];
            const float d = dinv[n];
            h[(size_t)n * HDIM + c] = a;
            agg[(size_t)n * HDIM + c] = a * d * d;
        }
    }
}

// K4: 64-wide message scatter. 16 threads/edge, one float4 vector-atomic each.
__global__ void k_scatter1(const int* __restrict__ row, const int* __restrict__ col,
                           const float* __restrict__ dinv,
                           const float* __restrict__ h,
                           float* __restrict__ agg, int E) {
    const long long idx = (long long)blockIdx.x * blockDim.x + threadIdx.x;
    const int e = (int)(idx >> 4);
    const int g = (int)(idx & 15);
    if (e >= E) return;
    const int r = row[e];
    const int c = col[e];
    const float w = dinv[r] * dinv[c];
    const float4 hv = *reinterpret_cast<const float4*>(&h[(size_t)r * HDIM + g * 4]);
    red_add_v4(&agg[(size_t)c * HDIM + g * 4],
               make_float4(hv.x * w, hv.y * w, hv.z * w, hv.w * w));
}

// K5: s[n] = relu(agg[n]+b1) . W2 ; out[n] = s[n]*dinv[n]^2 + b2  (self-loop init)
// warp per node
__global__ void k_layer2(const float* __restrict__ agg,
                         const float* __restrict__ b1,
                         const float* __restrict__ W2,
                         const float* __restrict__ b2,
                         const float* __restrict__ dinv,
                         float* __restrict__ s, float* __restrict__ out, int N) {
    const int warp = (blockIdx.x * blockDim.x + threadIdx.x) >> 5;
    const int lane = threadIdx.x & 31;
    if (warp >= N) return;
    const float a0 = agg[(size_t)warp * HDIM + lane] + b1[lane];
    const float a1 = agg[(size_t)warp * HDIM + 32 + lane] + b1[32 + lane];
    float v = fmaxf(a0, 0.0f) * W2[lane] + fmaxf(a1, 0.0f) * W2[32 + lane];
#pragma unroll
    for (int o = 16; o; o >>= 1) v += __shfl_xor_sync(0xffffffffu, v, o);
    if (lane == 0) {
        s[warp] = v;
        const float d = dinv[warp];
        out[warp] = v * d * d + b2[0];
    }
}

// K6: scalar scatter for layer 2: out[col] += s[row]*dinv[row]*dinv[col]
__global__ void k_scatter2(const int* __restrict__ row, const int* __restrict__ col,
                           const float* __restrict__ s,
                           const float* __restrict__ dinv,
                           float* __restrict__ out, int E) {
    const int e = blockIdx.x * blockDim.x + threadIdx.x;
    if (e >= E) return;
    const int r = row[e];
    const int c = col[e];
    atomicAdd(&out[c], s[r] * dinv[r] * dinv[c]);
}

extern "C" void kernel_launch(void* const* d_in, const int* in_sizes, int n_in,
                              void* d_out, int out_size) {
    const float* x  = (const float*)d_in[0];
    const void*  ei = d_in[1];                 // edge_index: int32 or int64, detected on-device
    const float* W1 = (const float*)d_in[2];
    const float* b1 = (const float*)d_in[3];
    const float* W2 = (const float*)d_in[4];
    const float* b2 = (const float*)d_in[5];
    float* out = (float*)d_out;

    const int N = in_sizes[0] / FDIM;
    const int E = in_sizes[1] / 2;

    float *deg, *dinv, *h, *agg, *s;
    int *row, *col;
    cudaGetSymbolAddress((void**)&deg,  g_deg);
    cudaGetSymbolAddress((void**)&dinv, g_dinv);
    cudaGetSymbolAddress((void**)&h,    g_h);
    cudaGetSymbolAddress((void**)&agg,  g_agg);
    cudaGetSymbolAddress((void**)&s,    g_s);
    cudaGetSymbolAddress((void**)&row,  g_row);
    cudaGetSymbolAddress((void**)&col,  g_col);

    const int T = 256;
    k_detect<<<1, 256>>>((const int*)ei, E);
    k_convert<<<(E + T - 1) / T, T>>>(ei, row, col, E);

    k_deg_init<<<(N + T - 1) / T, T>>>(deg, N);
    k_deg_count<<<(E + T - 1) / T, T>>>(col, deg, E);
    k_dinv<<<(N + T - 1) / T, T>>>(deg, dinv, N);

    k_gemm1<<<(N + 15) / 16, 64>>>(x, W1, dinv, h, agg, N);

    const long long s1_threads = (long long)E * 16;
    k_scatter1<<<(unsigned)((s1_threads + T - 1) / T), T>>>(row, col, dinv, h, agg, E);

    k_layer2<<<(N * 32 + T - 1) / T, T>>>(agg, b1, W2, b2, dinv, s, out, N);

    k_scatter2<<<(E + T - 1) / T, T>>>(row, col, s, dinv, out, E);
}

// round 3
// speedup vs baseline: 3.1730x; 3.1730x over previous
#include <cuda_runtime.h>
#include <cstdint>

// Problem constants (from setup_inputs): N=100000, F=128, H=64, E=1600000
#define FDIM 128
#define HDIM 64
#define MAXN 100096
#define MAXE 1600000

// Scratch (device globals — allocation-free per harness rules)
__device__ float g_hd[(size_t)MAXN * HDIM];  // (x @ W1) * dinv[row]
__device__ float g_sd[MAXN];                 // s * dinv
__device__ float g_dinv[MAXN];
__device__ int   g_degi[MAXN];
__device__ int   g_off[MAXN + 1];
__device__ int   g_cur[MAXN];
__device__ int   g_csr[MAXE];                // CSR-by-destination: source node ids
__device__ int   g_bsum[256];
__device__ int   g_is64;

// ---- packed f32x2 helpers (Blackwell FFMA2) ----
__device__ __forceinline__ void ffma2(unsigned long long& d,
                                      unsigned long long a, unsigned long long b) {
    asm("fma.rn.f32x2 %0, %1, %2, %0;" : "+l"(d) : "l"(a), "l"(b));
}
__device__ __forceinline__ unsigned long long pack2(float x, float y) {
    unsigned long long r;
    asm("mov.b64 %0, {%1, %2};" : "=l"(r) : "f"(x), "f"(y));
    return r;
}
__device__ __forceinline__ unsigned long long dup2(float x) {
    unsigned long long r;
    asm("mov.b64 %0, {%1, %1};" : "=l"(r) : "f"(x));
    return r;
}
__device__ __forceinline__ float2 unpk2(unsigned long long v) {
    float2 f;
    asm("mov.b64 {%0, %1}, %2;" : "=f"(f.x), "=f"(f.y) : "l"(v));
    return f;
}

// K_detect: int64 vs int32 edge_index. If int64 (LE), odd 32-bit words are high
// halves of values in [0,N) -> all zero. If int32, they're random node ids.
__global__ void k_detect(const int* __restrict__ raw, int E) {
    __shared__ int any_nonzero;
    if (threadIdx.x == 0) any_nonzero = 0;
    __syncthreads();
    const int stride = (2 * E) / 256;
    int idx = 2 * (threadIdx.x * (stride / 2)) + 1;
    if (idx < 2 * E && raw[idx] != 0) atomicOr(&any_nonzero, 1);
    __syncthreads();
    if (threadIdx.x == 0) g_is64 = any_nonzero ? 0 : 1;
}

__device__ __forceinline__ int load_idx(const void* ei, size_t pos) {
    return g_is64 ? (int)((const long long*)ei)[pos] : ((const int*)ei)[pos];
}

__global__ void k_zero(int* degi, int N) {
    int i = blockIdx.x * blockDim.x + threadIdx.x;
    if (i < N) degi[i] = 0;
}

// degree count at destinations (col)
__global__ void k_count(const void* __restrict__ ei, int* __restrict__ degi, int E) {
    int e = blockIdx.x * blockDim.x + threadIdx.x;
    if (e < E) atomicAdd(&degi[load_idx(ei, (size_t)E + e)], 1);
}

// ---- exclusive scan of degi -> off (3 kernels) ----
__global__ void k_scan_block(const int* __restrict__ degi, int* __restrict__ off,
                             int* __restrict__ bsum, int N) {
    __shared__ int wsum[32];
    const int i = blockIdx.x * 1024 + threadIdx.x;
    const int lane = threadIdx.x & 31, wid = threadIdx.x >> 5;
    int v = (i < N) ? degi[i] : 0;
    int s = v;
#pragma unroll
    for (int o = 1; o < 32; o <<= 1) {
        int t = __shfl_up_sync(0xffffffffu, s, o);
        if (lane >= o) s += t;
    }
    if (lane == 31) wsum[wid] = s;
    __syncthreads();
    if (wid == 0) {
        int ws = wsum[lane];
#pragma unroll
        for (int o = 1; o < 32; o <<= 1) {
            int t = __shfl_up_sync(0xffffffffu, ws, o);
            if (lane >= o) ws += t;
        }
        wsum[lane] = ws;
    }
    __syncthreads();
    int excl = s - v + (wid ? wsum[wid - 1] : 0);
    if (i < N) off[i] = excl;
    if (threadIdx.x == 1023) bsum[blockIdx.x] = excl + v;
}

__global__ void k_scan_top(int* bsum, int nb) {
    __shared__ int sm[1024];
    int t = threadIdx.x;
    sm[t] = (t < nb) ? bsum[t] : 0;
    __syncthreads();
    for (int o = 1; o < 1024; o <<= 1) {
        int v = (t >= o) ? sm[t - o] : 0;
        __syncthreads();
        sm[t] += v;
        __syncthreads();
    }
    if (t < nb) bsum[t] = sm[t];  // inclusive
}

__global__ void k_scan_add(int* __restrict__ off, const int* __restrict__ bsum,
                           int* __restrict__ cur, float* __restrict__ dinv,
                           const int* __restrict__ degi, int N, int E) {
    int i = blockIdx.x * 1024 + threadIdx.x;
    if (i < N) {
        int add = blockIdx.x ? bsum[blockIdx.x - 1] : 0;
        int o = off[i] + add;
        off[i] = o;
        cur[i] = o;
        dinv[i] = rsqrtf((float)(degi[i] + 1));  // +1 self loop
    }
    if (blockIdx.x == 0 && threadIdx.x == 0) off[N] = E;
}

// fill CSR buckets: csr[pos] = source(row)
__global__ void k_fill(const void* __restrict__ ei, int* __restrict__ cur,
                       int* __restrict__ csr, int E) {
    int e = blockIdx.x * blockDim.x + threadIdx.x;
    if (e >= E) return;
    int r = load_idx(ei, e);
    int c = load_idx(ei, (size_t)E + e);
    int pos = atomicAdd(&cur[c], 1);
    csr[pos] = r;
}

// GEMM: hd[n] = (x[n] @ W1) * dinv[n]. Block=128 threads, 32 rows, f32x2 FMA.
__global__ void __launch_bounds__(128) k_gemm(const float* __restrict__ x,
                                              const float* __restrict__ W1,
                                              const float* __restrict__ dinv,
                                              float* __restrict__ hd, int N) {
    __shared__ float Xs[32 * 64];  // 8KB: 32 rows x 64 k
    __shared__ float Ws[64 * 64];  // 16KB: 64 k x 64 cols
    const int tid = threadIdx.x;
    const int cg = tid & 15;   // col group: cols 4cg..4cg+3
    const int rg = tid >> 4;   // row group: rows 4rg..4rg+3 (rg 0..7)
    const int row0 = blockIdx.x * 32;
    const int rows = min(32, N - row0);

    if (rows == 32) {
        unsigned long long acc[4][2] = {};
        for (int kb = 0; kb < FDIM; kb += 64) {
            __syncthreads();
            // stage x tile (32 rows x 64 k), coalesced float4
            for (int i = tid; i < 512; i += 128) {
                int r = i >> 4, k4 = i & 15;
                ((float4*)Xs)[i] = *(const float4*)&x[(size_t)(row0 + r) * FDIM + kb + k4 * 4];
            }
            // stage W tile (64 k x 64 cols)
            for (int i = tid; i < 1024; i += 128) {
                int k = i >> 4, c4 = i & 15;
                ((float4*)Ws)[i] = *(const float4*)&W1[(size_t)(kb + k) * HDIM + c4 * 4];
            }
            __syncthreads();
#pragma unroll 4
            for (int k = 0; k < 64; k++) {
                const float4 wv = ((const float4*)Ws)[k * 16 + cg];
                const unsigned long long w01 = pack2(wv.x, wv.y);
                const unsigned long long w23 = pack2(wv.z, wv.w);
#pragma unroll
                for (int i = 0; i < 4; i++) {
                    const unsigned long long a2 = dup2(Xs[(rg * 4 + i) * 64 + k]);
                    ffma2(acc[i][0], a2, w01);
                    ffma2(acc[i][1], a2, w23);
                }
            }
        }
#pragma unroll
        for (int i = 0; i < 4; i++) {
            const int n = row0 + rg * 4 + i;
            const float dn = dinv[n];
            const float2 p = unpk2(acc[i][0]);
            const float2 q = unpk2(acc[i][1]);
            *(float4*)&hd[(size_t)n * HDIM + cg * 4] =
                make_float4(p.x * dn, p.y * dn, q.x * dn, q.y * dn);
        }
    } else {
        for (int r = rg; r < rows; r += 8) {
            const int n = row0 + r;
            const float dn = dinv[n];
            for (int cc = cg * 4; cc < cg * 4 + 4; cc++) {
                float a = 0.0f;
                for (int k = 0; k < FDIM; k++)
                    a += x[(size_t)n * FDIM + k] * W1[(size_t)k * HDIM + cc];
                hd[(size_t)n * HDIM + cc] = a * dn;
            }
        }
    }
}

// gather1: per node c (16-lane group, float4/lane):
//   acc = hd[c] + sum_{j in CSR[c]} hd[src];  t = acc*dinv[c];
//   s = sum relu(t + b1)*W2 (16-lane reduce);  sd[c] = s*dinv[c]
__global__ void k_gather1(const int* __restrict__ off, const int* __restrict__ csr,
                          const float* __restrict__ hd, const float* __restrict__ dinv,
                          const float* __restrict__ b1, const float* __restrict__ W2,
                          float* __restrict__ sd, int N) {
    const int t = blockIdx.x * blockDim.x + threadIdx.x;
    const int c = t >> 4;
    const int g = t & 15;
    if (c >= N) return;
    const int s0 = off[c], s1 = off[c + 1];
    const float4* hp = (const float4*)hd;
    float4 acc = hp[(size_t)c * 16 + g];  // self loop (hd = h*dinv already)
    int j = s0;
    for (; j + 2 <= s1; j += 2) {
        const int r0 = csr[j], r1 = csr[j + 1];
        const float4 a = hp[(size_t)r0 * 16 + g];
        const float4 b = hp[(size_t)r1 * 16 + g];
        acc.x += a.x; acc.y += a.y; acc.z += a.z; acc.w += a.w;
        acc.x += b.x; acc.y += b.y; acc.z += b.z; acc.w += b.w;
    }
    if (j < s1) {
        const float4 a = hp[(size_t)csr[j] * 16 + g];
        acc.x += a.x; acc.y += a.y; acc.z += a.z; acc.w += a.w;
    }
    const float dc = dinv[c];
    const float4 bv = ((const float4*)b1)[g];
    const float4 wv = ((const float4*)W2)[g];
    float v = fmaxf(acc.x * dc + bv.x, 0.0f) * wv.x
            + fmaxf(acc.y * dc + bv.y, 0.0f) * wv.y
            + fmaxf(acc.z * dc + bv.z, 0.0f) * wv.z
            + fmaxf(acc.w * dc + bv.w, 0.0f) * wv.w;
    const unsigned mask = 0xFFFFu << (threadIdx.x & 16);
    v += __shfl_xor_sync(mask, v, 8);
    v += __shfl_xor_sync(mask, v, 4);
    v += __shfl_xor_sync(mask, v, 2);
    v += __shfl_xor_sync(mask, v, 1);
    if (g == 0) sd[c] = v * dc;
}

// gather2: out[c] = dinv[c]*(sd[c] + sum_{j} sd[src_j]) + b2
__global__ void k_gather2(const int* __restrict__ off, const int* __restrict__ csr,
                          const float* __restrict__ sd, const float* __restrict__ dinv,
                          const float* __restrict__ b2, float* __restrict__ out, int N) {
    const int t = blockIdx.x * blockDim.x + threadIdx.x;
    const int c = t >> 4;
    const int g = t & 15;
    if (c >= N) return;
    const int s0 = off[c], s1 = off[c + 1];
    float acc = (g == 0) ? sd[c] : 0.0f;
    for (int j = s0 + g; j < s1; j += 16) acc += sd[csr[j]];
    const unsigned mask = 0xFFFFu << (threadIdx.x & 16);
    acc += __shfl_xor_sync(mask, acc, 8);
    acc += __shfl_xor_sync(mask, acc, 4);
    acc += __shfl_xor_sync(mask, acc, 2);
    acc += __shfl_xor_sync(mask, acc, 1);
    if (g == 0) out[c] = acc * dinv[c] + b2[0];
}

extern "C" void kernel_launch(void* const* d_in, const int* in_sizes, int n_in,
                              void* d_out, int out_size) {
    const float* x  = (const float*)d_in[0];
    const void*  ei = d_in[1];  // int32 or int64, detected on-device
    const float* W1 = (const float*)d_in[2];
    const float* b1 = (const float*)d_in[3];
    const float* W2 = (const float*)d_in[4];
    const float* b2 = (const float*)d_in[5];
    float* out = (float*)d_out;

    const int N = in_sizes[0] / FDIM;
    const int E = in_sizes[1] / 2;

    float *hd, *sd, *dinv;
    int *degi, *off, *cur, *csr, *bsum;
    cudaGetSymbolAddress((void**)&hd,   g_hd);
    cudaGetSymbolAddress((void**)&sd,   g_sd);
    cudaGetSymbolAddress((void**)&dinv, g_dinv);
    cudaGetSymbolAddress((void**)&degi, g_degi);
    cudaGetSymbolAddress((void**)&off,  g_off);
    cudaGetSymbolAddress((void**)&cur,  g_cur);
    cudaGetSymbolAddress((void**)&csr,  g_csr);
    cudaGetSymbolAddress((void**)&bsum, g_bsum);

    const int T = 256;
    const int nb = (N + 1023) / 1024;

    k_detect<<<1, 256>>>((const int*)ei, E);
    k_zero<<<(N + T - 1) / T, T>>>(degi, N);
    k_count<<<(E + T - 1) / T, T>>>(ei, degi, E);
    k_scan_block<<<nb, 1024>>>(degi, off, bsum, N);
    k_scan_top<<<1, 1024>>>(bsum, nb);
    k_scan_add<<<nb, 1024>>>(off, bsum, cur, dinv, degi, N, E);
    k_gemm<<<(N + 31) / 32, 128>>>(x, W1, dinv, hd, N);
    k_fill<<<(E + T - 1) / T, T>>>(ei, cur, csr, E);

    const int groups = N * 16;
    k_gather1<<<(groups + T - 1) / T, T>>>(off, csr, hd, dinv, b1, W2, sd, N);
    k_gather2<<<(groups + T - 1) / T, T>>>(off, csr, sd, dinv, b2, out, N);
}